// round 15
// baseline (speedup 1.0000x reference)
#include <cuda_runtime.h>

#define MARGIN 1.0
#define TPB 512
#define NSLICE 256               // negatives per block (= TPB / 2 groups)
#define SEG 8192                 // elements per compaction segment (smem cap)
#define VEC4 (SEG / (TPB * 4))   // float4 loads per thread per segment = 4
#define NWARPS (TPB / 32)
#define NRED 6                   // fused reduction width

// Accumulating globals: zero-initialized at load, reset by the finalizer
// after each run so graph replays start clean with no extra launch.
__device__ double g_sabs;                  // sum |a_i + n_j| over pairs
__device__ double g_s, g_s2, g_sp, g_sp2;  // sum p, p^2 (all); sum p, p^2 (pos)
__device__ int g_pc;                       // positive count
__device__ int g_done;

__device__ __forceinline__ unsigned long long packf2(float lo, float hi) {
    unsigned long long r;
    asm("mov.b64 %0, {%1, %2};" : "=l"(r) : "f"(lo), "f"(hi));
    return r;
}
__device__ __forceinline__ void unpackf2(float& lo, float& hi, unsigned long long v) {
    asm("mov.b64 {%0, %1}, %2;" : "=f"(lo), "=f"(hi) : "l"(v));
}
__device__ __forceinline__ unsigned long long addf2(unsigned long long a,
                                                    unsigned long long b) {
    unsigned long long r;
    asm("add.rn.f32x2 %0, %1, %2;" : "=l"(r) : "l"(a), "l"(b));
    return r;
}

__global__ void __launch_bounds__(TPB)
aucm_kernel(const float* __restrict__ preds, const int* __restrict__ targets,
            int n, float* __restrict__ out, int nblocks) {
    __shared__ float sa[SEG];            // compacted (1 - p) of segment positives
    __shared__ int ws[NWARPS];
    __shared__ float wred[NWARPS][NRED]; // fused per-warp reduction rows

    const int tid = threadIdx.x;
    const int lane = tid & 31;
    const int wid = tid >> 5;
    const int g = tid >> 8;          // positive-split group (0/1)

    // This thread's owned element (two threads per element, one per group).
    const int ni = blockIdx.x * NSLICE + (tid & (NSLICE - 1));
    float nv = 0.0f;
    int tgt = -1;                    // -1 = out of bounds
    if (ni < n) {
        nv = preds[ni];
        tgt = targets[ni];
    }
    const int isneg = (tgt == 0);
    const int ispos = (tgt == 1);
    const unsigned long long nv2 = packf2(nv, nv);
    const unsigned long long ABSM = 0x7FFFFFFF7FFFFFFFull;

    unsigned long long acc0 = 0ull, acc1 = 0ull;   // packed accumulators
    float accs = 0.0f;                              // scalar tail

    for (int s0 = 0; s0 < n; s0 += SEG) {
        // ---- Stage this thread's slice of the segment; flag positives ----
        float pv[VEC4 * 4];
        unsigned int fmask = 0;
        int c = 0;
        #pragma unroll
        for (int v = 0; v < VEC4; v++) {
            const int j = s0 + (v * TPB + tid) * 4;
            float4 p4 = make_float4(0.f, 0.f, 0.f, 0.f);
            int4 t4 = make_int4(-1, -1, -1, -1);
            if (j + 4 <= n) {
                p4 = *(const float4*)(preds + j);
                t4 = *(const int4*)(targets + j);
            } else {
                float* pp = (float*)&p4;
                int* tt = (int*)&t4;
                for (int k = 0; k < 4; k++)
                    if (j + k < n) { pp[k] = preds[j + k]; tt[k] = targets[j + k]; }
            }
            const float* pp = (const float*)&p4;
            const int* tt = (const int*)&t4;
            #pragma unroll
            for (int k = 0; k < 4; k++) {
                pv[v * 4 + k] = pp[k];
                int f = (tt[k] == 1);
                fmask |= (unsigned)f << (v * 4 + k);
                c += f;
            }
        }

        // ---- Block scan of positive counts -> compaction offsets ----
        int inc = c;
        #pragma unroll
        for (int off = 1; off < 32; off <<= 1) {
            int u = __shfl_up_sync(0xFFFFFFFFu, inc, off);
            if (lane >= off) inc += u;
        }
        if (lane == 31) ws[wid] = inc;
        __syncthreads();
        if (wid == 0) {
            int v = (lane < NWARPS) ? ws[lane] : 0;
            #pragma unroll
            for (int off = 1; off < NWARPS; off <<= 1) {
                int u = __shfl_up_sync(0xFFFFFFFFu, v, off);
                if (lane >= off) v += u;
            }
            if (lane < NWARPS) ws[lane] = v;
        }
        __syncthreads();
        int wr = ((wid == 0) ? 0 : ws[wid - 1]) + inc - c;
        const int tpos = ws[NWARPS - 1];

        #pragma unroll
        for (int k = 0; k < VEC4 * 4; k++)
            if ((fmask >> k) & 1u) sa[wr++] = 1.0f - pv[k];
        __syncthreads();

        // ---- Pair loop: my negative vs all segment positives (split by g) ----
        if (isneg) {
            const int t4n = tpos >> 2;
            const float4* sa4 = (const float4*)sa;
            #pragma unroll 2
            for (int jj = g; jj < t4n; jj += 2) {
                const float4 s = sa4[jj];
                unsigned long long d0 = addf2(packf2(s.x, s.y), nv2);
                unsigned long long d1 = addf2(packf2(s.z, s.w), nv2);
                d0 &= ABSM;                           // |d| on both lanes
                d1 &= ABSM;
                acc0 = addf2(acc0, d0);
                acc1 = addf2(acc1, d1);
            }
            if (g == 0)
                for (int j = t4n << 2; j < tpos; j++)
                    accs += fabsf(sa[j] + nv);
        }
        __syncthreads();   // sa/ws reused next segment
    }

    // ---- Fused epilogue: reduce 6 values with ONE barrier ----
    float a0l, a0h, a1l, a1h;
    unpackf2(a0l, a0h, acc0);
    unpackf2(a1l, a1h, acc1);

    const bool own = (g == 0) && (tgt >= 0);   // element counted once
    float rv[NRED];
    rv[0] = accs + (a0l + a0h) + (a1l + a1h);          // sum |d| contribution
    rv[1] = own ? nv : 0.0f;                            // sum p   (all)
    rv[2] = own ? nv * nv : 0.0f;                       // sum p^2 (all)
    rv[3] = (own && ispos) ? nv : 0.0f;                 // sum p   (pos)
    rv[4] = (own && ispos) ? nv * nv : 0.0f;            // sum p^2 (pos)
    rv[5] = (own && ispos) ? 1.0f : 0.0f;               // positive count

    #pragma unroll
    for (int q = 0; q < NRED; q++) {
        #pragma unroll
        for (int off = 16; off > 0; off >>= 1)
            rv[q] += __shfl_xor_sync(0xFFFFFFFFu, rv[q], off);
    }
    if (lane == 0) {
        #pragma unroll
        for (int q = 0; q < NRED; q++) wred[wid][q] = rv[q];
    }
    __syncthreads();

    if (wid == 0) {
        float fv[NRED];
        #pragma unroll
        for (int q = 0; q < NRED; q++)
            fv[q] = (lane < NWARPS) ? wred[lane][q] : 0.0f;
        #pragma unroll
        for (int q = 0; q < NRED; q++) {
            #pragma unroll
            for (int off = NWARPS / 2; off > 0; off >>= 1)
                fv[q] += __shfl_xor_sync(0xFFFFFFFFu, fv[q], off);
        }
        if (lane == 0) {
            atomicAdd(&g_sabs, (double)fv[0]);
            atomicAdd(&g_s, (double)fv[1]);
            atomicAdd(&g_s2, (double)fv[2]);
            atomicAdd(&g_sp, (double)fv[3]);
            atomicAdd(&g_sp2, (double)fv[4]);
            atomicAdd(&g_pc, (int)(fv[5] + 0.5f));
            __threadfence();                 // release my contributions
            int prev = atomicAdd(&g_done, 1);
            if (prev == nblocks - 1) {
                __threadfence();             // acquire all contributions
                double Pp = (double)g_pc;
                double Nn = (double)n - Pp;
                double Sp = g_sp, Sp2 = g_sp2;
                double Sa = Pp - Sp;                      // sum (1-p) over pos
                double Sa2 = Pp - 2.0 * Sp + Sp2;         // sum (1-p)^2 over pos
                double Sn = g_s - Sp;                     // sum over negatives
                double Sn2 = g_s2 - Sp2;                  // sum sq over negatives
                double Sd = Nn * Sa + Pp * Sn;            // sum d over pairs
                double Squad = Nn * Sa2 + 2.0 * Sa * Sn + Pp * Sn2;
                double Srelu = 0.5 * (Sd + g_sabs);       // relu = (d + |d|)/2
                double total = Squad + MARGIN * Srelu;
                out[0] = (float)(total / (Pp * Nn));
                // Reset all accumulating globals for the next graph replay.
                g_sabs = 0.0;
                g_s = 0.0; g_s2 = 0.0; g_sp = 0.0; g_sp2 = 0.0;
                g_pc = 0;
                g_done = 0;
            }
        }
    }
}

extern "C" void kernel_launch(void* const* d_in, const int* in_sizes, int n_in,
                              void* d_out, int out_size) {
    const float* preds = (const float*)d_in[0];
    const int* targets = (const int*)d_in[1];
    float* out = (float*)d_out;
    int n = in_sizes[0];

    int gx = (n + NSLICE - 1) / NSLICE;   // 64 for n=16384
    aucm_kernel<<<gx, TPB>>>(preds, targets, n, out, gx);
}

// round 17
// speedup vs baseline: 1.4613x; 1.4613x over previous
#include <cuda_runtime.h>

#define MARGIN 1.0
#define TPB 256
#define TILE 1024
#define PER 4                    // tile elements per thread
#define NWARPS (TPB / 32)
#define NRED 6                   // fused reduction width

// Accumulating globals: zero-initialized at load, reset by the finalizer
// after each run so graph replays start clean with no extra launch.
__device__ double g_sabs;                  // sum |a_i + n_j| over pairs
__device__ double g_s, g_s2, g_sp, g_sp2;  // sum p, p^2 (all); sum p, p^2 (pos)
__device__ int g_pc;                       // positive count
__device__ int g_done;

__device__ __forceinline__ unsigned long long packf2(float lo, float hi) {
    unsigned long long r;
    asm("mov.b64 %0, {%1, %2};" : "=l"(r) : "f"(lo), "f"(hi));
    return r;
}
__device__ __forceinline__ void unpackf2(float& lo, float& hi, unsigned long long v) {
    asm("mov.b64 {%0, %1}, %2;" : "=f"(lo), "=f"(hi) : "l"(v));
}
__device__ __forceinline__ unsigned long long addf2(unsigned long long a,
                                                    unsigned long long b) {
    unsigned long long r;
    asm("add.rn.f32x2 %0, %1, %2;" : "=l"(r) : "l"(a), "l"(b));
    return r;
}

__global__ void __launch_bounds__(TPB)
aucm_kernel(const float* __restrict__ preds, const int* __restrict__ targets,
            int n, float* __restrict__ out, int nblocks) {
    __shared__ float sa[TILE];            // compacted (1 - p) of tile positives
    __shared__ int ws[NWARPS];
    __shared__ float wred[NWARPS][NRED];  // fused per-warp reduction rows

    const int tid = threadIdx.x;
    const int lane = tid & 31;
    const int wid = tid >> 5;

    // This thread's owned element (its candidate negative).
    const int ni = blockIdx.x * TPB + tid;
    float nv = 0.0f;
    int tgt = -1;                 // -1 = out of bounds
    if (ni < n) {
        nv = preds[ni];
        tgt = targets[ni];
    }
    const int isneg = (tgt == 0);
    const int ispos = (tgt == 1);
    const unsigned long long nv2 = packf2(nv, nv);
    const unsigned long long ABSM = 0x7FFFFFFF7FFFFFFFull;

    // ---- Load this block's positive tile [j0, j1); flag positives ----
    const int j0 = blockIdx.y * TILE;
    const int j1 = min(j0 + TILE, n);
    float pv[PER];
    int fl[PER];
    int c = 0;
    if (j1 - j0 == TILE) {
        const float4 p4 = ((const float4*)(preds + j0))[tid];
        const int4 t4 = ((const int4*)(targets + j0))[tid];
        pv[0] = p4.x; pv[1] = p4.y; pv[2] = p4.z; pv[3] = p4.w;
        fl[0] = (t4.x == 1); fl[1] = (t4.y == 1);
        fl[2] = (t4.z == 1); fl[3] = (t4.w == 1);
        c = fl[0] + fl[1] + fl[2] + fl[3];
    } else {
        #pragma unroll
        for (int k = 0; k < PER; k++) {
            int j = j0 + tid * PER + k;
            float p = 0.0f; int f = 0;
            if (j < j1) { p = preds[j]; f = (targets[j] == 1); }
            pv[k] = p; fl[k] = f; c += f;
        }
    }

    // ---- Block scan of positive counts -> compaction offsets ----
    int inc = c;
    #pragma unroll
    for (int off = 1; off < 32; off <<= 1) {
        int u = __shfl_up_sync(0xFFFFFFFFu, inc, off);
        if (lane >= off) inc += u;
    }
    if (lane == 31) ws[wid] = inc;
    __syncthreads();
    if (wid == 0) {
        int v = (lane < NWARPS) ? ws[lane] : 0;
        #pragma unroll
        for (int off = 1; off < NWARPS; off <<= 1) {
            int u = __shfl_up_sync(0xFFFFFFFFu, v, off);
            if (lane >= off) v += u;
        }
        if (lane < NWARPS) ws[lane] = v;
    }
    __syncthreads();
    int wr = ((wid == 0) ? 0 : ws[wid - 1]) + inc - c;
    const int tpos = ws[NWARPS - 1];
    #pragma unroll
    for (int k = 0; k < PER; k++)
        if (fl[k]) sa[wr++] = 1.0f - pv[k];
    __syncthreads();

    // ---- Pair loop: my negative vs all tile positives, f32x2 packed ----
    unsigned long long acc0 = 0ull, acc1 = 0ull;
    float accs = 0.0f;
    if (isneg) {
        const unsigned long long* sa2 = (const unsigned long long*)sa;
        const int t2 = tpos >> 1;        // pairs of positives
        int jj = 0;
        for (; jj + 2 <= t2; jj += 2) {
            unsigned long long d0 = addf2(sa2[jj], nv2) & ABSM;
            unsigned long long d1 = addf2(sa2[jj + 1], nv2) & ABSM;
            acc0 = addf2(acc0, d0);
            acc1 = addf2(acc1, d1);
        }
        if (jj < t2)
            acc0 = addf2(acc0, addf2(sa2[jj], nv2) & ABSM);
        if (tpos & 1)
            accs = fabsf(sa[tpos - 1] + nv);
    }

    // ---- Fused epilogue (single barrier). Stats only in y==0 blocks. ----
    float a0l, a0h, a1l, a1h;
    unpackf2(a0l, a0h, acc0);
    unpackf2(a1l, a1h, acc1);
    float main_v = accs + (a0l + a0h) + (a1l + a1h);   // sum |d| contribution

    const bool stats_blk = (blockIdx.y == 0);          // block-uniform
    const bool own = stats_blk && (tgt >= 0);          // element counted once

    if (stats_blk) {
        float rv[NRED];
        rv[0] = main_v;
        rv[1] = own ? nv : 0.0f;                        // sum p   (all)
        rv[2] = own ? nv * nv : 0.0f;                   // sum p^2 (all)
        rv[3] = (own && ispos) ? nv : 0.0f;             // sum p   (pos)
        rv[4] = (own && ispos) ? nv * nv : 0.0f;        // sum p^2 (pos)
        rv[5] = (own && ispos) ? 1.0f : 0.0f;           // positive count
        #pragma unroll
        for (int q = 0; q < NRED; q++) {
            #pragma unroll
            for (int off = 16; off > 0; off >>= 1)
                rv[q] += __shfl_xor_sync(0xFFFFFFFFu, rv[q], off);
        }
        if (lane == 0) {
            #pragma unroll
            for (int q = 0; q < NRED; q++) wred[wid][q] = rv[q];
        }
        __syncthreads();
        if (wid == 0) {
            float fv[NRED];
            #pragma unroll
            for (int q = 0; q < NRED; q++)
                fv[q] = (lane < NWARPS) ? wred[lane][q] : 0.0f;
            #pragma unroll
            for (int q = 0; q < NRED; q++) {
                #pragma unroll
                for (int off = NWARPS / 2; off > 0; off >>= 1)
                    fv[q] += __shfl_xor_sync(0xFFFFFFFFu, fv[q], off);
            }
            if (lane == 0) {
                atomicAdd(&g_sabs, (double)fv[0]);
                atomicAdd(&g_s, (double)fv[1]);
                atomicAdd(&g_s2, (double)fv[2]);
                atomicAdd(&g_sp, (double)fv[3]);
                atomicAdd(&g_sp2, (double)fv[4]);
                atomicAdd(&g_pc, (int)(fv[5] + 0.5f));
            }
        }
    } else {
        float v = main_v;
        #pragma unroll
        for (int off = 16; off > 0; off >>= 1)
            v += __shfl_xor_sync(0xFFFFFFFFu, v, off);
        if (lane == 0) wred[wid][0] = v;
        __syncthreads();
        if (wid == 0) {
            v = (lane < NWARPS) ? wred[lane][0] : 0.0f;
            #pragma unroll
            for (int off = NWARPS / 2; off > 0; off >>= 1)
                v += __shfl_xor_sync(0xFFFFFFFFu, v, off);
            if (lane == 0) atomicAdd(&g_sabs, (double)v);
        }
    }

    if (tid == 0) {
        __threadfence();                 // release my contributions
        int prev = atomicAdd(&g_done, 1);
        if (prev == nblocks - 1) {
            __threadfence();             // acquire all contributions
            double Pp = (double)g_pc;
            double Nn = (double)n - Pp;
            double Sp = g_sp, Sp2 = g_sp2;
            double Sa = Pp - Sp;                      // sum (1-p) over pos
            double Sa2 = Pp - 2.0 * Sp + Sp2;         // sum (1-p)^2 over pos
            double Sn = g_s - Sp;                     // sum over negatives
            double Sn2 = g_s2 - Sp2;                  // sum sq over negatives
            double Sd = Nn * Sa + Pp * Sn;            // sum d over pairs
            double Squad = Nn * Sa2 + 2.0 * Sa * Sn + Pp * Sn2;
            double Srelu = 0.5 * (Sd + g_sabs);       // relu = (d + |d|)/2
            double total = Squad + MARGIN * Srelu;
            out[0] = (float)(total / (Pp * Nn));
            // Reset all accumulating globals for the next graph replay.
            g_sabs = 0.0;
            g_s = 0.0; g_s2 = 0.0; g_sp = 0.0; g_sp2 = 0.0;
            g_pc = 0;
            g_done = 0;
        }
    }
}

extern "C" void kernel_launch(void* const* d_in, const int* in_sizes, int n_in,
                              void* d_out, int out_size) {
    const float* preds = (const float*)d_in[0];
    const int* targets = (const int*)d_in[1];
    float* out = (float*)d_out;
    int n = in_sizes[0];

    dim3 grid((n + TPB - 1) / TPB, (n + TILE - 1) / TILE);   // (64, 16) = 1024
    aucm_kernel<<<grid, TPB>>>(preds, targets, n, out,
                               (int)(grid.x * grid.y));
}